// round 4
// baseline (speedup 1.0000x reference)
#include <cuda_runtime.h>
#include <cstdint>

#define W_IMG 512
#define H_IMG 512
#define HW    (512*512)
#define NB    4
#define EPS   1e-5f

#define TILE_W 128
#define TILE_H 8
#define BX 32
#define BY 8
#define NTHREADS (BX*BY)
#define PPT 4
#define HALO 2
#define SM_W (TILE_W + 2*HALO)   // 132
#define SM_H (TILE_H + 2*HALO)   // 12

#define NPROD 128                 // gray-max producer blocks (must be < 148: wave-1 safe)
#define CH_PB (NPROD / NB)        // 32 chunks per batch
#define NBLK_MAIN (NB * (H_IMG/TILE_H) * (W_IMG/TILE_W))    // 1024

// scratch (no device allocs) — rewritten every replay; g_count reset by finalize
__device__ float g_gmax_partial[NPROD];
__device__ int   g_count;                 // zero at module load; finalize resets to 0
__device__ float g_blockA[NBLK_MAIN];
__device__ float g_blockB[NBLK_MAIN];

__global__ __launch_bounds__(NTHREADS, 2)
void intensity_loss_main(const float* __restrict__ fake,
                         const float* __restrict__ gamma_hdr,
                         const float* __restrict__ hdr_im,
                         const float* __restrict__ r_weights,
                         const float* __restrict__ f_factors,
                         const float* __restrict__ gray) {
    cudaTriggerProgrammaticLaunchCompletion();   // let PDL'd finalize spin up early

    __shared__ __align__(16) float sf[SM_H * SM_W];
    __shared__ __align__(16) float sg[SM_H * SM_W];
    __shared__ __align__(16) float sh[SM_H * SM_W];
    __shared__ float redA[BY], redB[BY];
    __shared__ float s_gmax;

    const int b     = blockIdx.z;
    const int wbase = blockIdx.x * TILE_W;
    const int hbase = blockIdx.y * TILE_H;
    const int tid   = threadIdx.y * BX + threadIdx.x;
    const int lbid  = blockIdx.x + 4 * (blockIdx.y + 64 * blockIdx.z);  // linear bid

    // ---- producer path: first NPROD blocks compute gray-max partials FIRST ----
    // (wave-1 resident by construction: NPROD=128 < 148 SMs even at occ=1)
    if (lbid < NPROD) {
        const int gb    = lbid / CH_PB;
        const int chunk = lbid - gb * CH_PB;
        const float4* p4 = reinterpret_cast<const float4*>(gray + (size_t)gb * HW);
        const int base = chunk * 2048;            // 2048 float4 per chunk
        float m = 0.0f;
#pragma unroll
        for (int k = 0; k < 8; k++) {
            float4 v = p4[base + tid + k * 256];
            m = fmaxf(m, fmaxf(fmaxf(v.x, v.y), fmaxf(v.z, v.w)));
        }
#pragma unroll
        for (int o = 16; o > 0; o >>= 1)
            m = fmaxf(m, __shfl_down_sync(0xFFFFFFFFu, m, o));
        if ((tid & 31) == 0) redA[tid >> 5] = m;
        __syncthreads();
        if (tid == 0) {
            float mm = redA[0];
#pragma unroll
            for (int w = 1; w < BY; w++) mm = fmaxf(mm, redA[w]);
            g_gmax_partial[lbid] = mm;
            __threadfence();
            atomicAdd(&g_count, 1);
        }
        __syncthreads();   // redA reused later
    }

    const float ff   = f_factors[b];
    const float expo = 1.0f - ff;

    const float* fp = fake      + (size_t)b * HW;
    const float* gp = gamma_hdr + (size_t)b * HW;
    const float* hp = hdr_im    + (size_t)b * HW;

    const int lw  = threadIdx.x * PPT;
    const int lh  = threadIdx.y;
    const int gw0 = wbase + lw;
    const int gh  = hbase + lh;
    const float* rwp = r_weights + (size_t)b * 25 * HW + (size_t)gh * W_IMG + gw0;

    // ---- issue r_weights row di=0 BEFORE staging: DRAM busy during powf ----
    float4 cur[5];
#pragma unroll
    for (int j = 0; j < 5; j++)
        cur[j] = *reinterpret_cast<const float4*>(rwp + (size_t)j * HW);

    // stage tile + halo (zero-pad OOB); hdr gets pow applied here
    for (int i = tid; i < SM_H * SM_W; i += NTHREADS) {
        const int r  = i / SM_W;
        const int c  = i - r * SM_W;
        const int ghh = hbase + r - HALO;
        const int gww = wbase + c - HALO;
        float vf = 0.0f, vg = 0.0f, vh = 0.0f;
        if (ghh >= 0 && ghh < H_IMG && gww >= 0 && gww < W_IMG) {
            const int gi = ghh * W_IMG + gww;
            vf = fp[gi];
            vg = gp[gi];
            vh = __powf(hp[gi], expo);
        }
        sf[i] = vf; sg[i] = vg; sh[i] = vh;
    }
    __syncthreads();

    float s1f[PPT] = {0,0,0,0}, s2f[PPT] = {0,0,0,0};
    float s1g[PPT] = {0,0,0,0}, s2g[PPT] = {0,0,0,0};
    float s1h[PPT] = {0,0,0,0}, ws [PPT] = {0,0,0,0};

#pragma unroll
    for (int di = 0; di < 5; di++) {
        // prefetch next tap-row while consuming current (MLP >= 5 on rw stream)
        float4 nxt[5];
        if (di < 4) {
#pragma unroll
            for (int j = 0; j < 5; j++)
                nxt[j] = *reinterpret_cast<const float4*>(rwp + (size_t)((di + 1) * 5 + j) * HW);
        }

        const int rowoff = (lh + di) * SM_W + lw;   // 16B-aligned
        const float4 f0 = *reinterpret_cast<const float4*>(&sf[rowoff]);
        const float4 f1 = *reinterpret_cast<const float4*>(&sf[rowoff + 4]);
        const float4 g0 = *reinterpret_cast<const float4*>(&sg[rowoff]);
        const float4 g1 = *reinterpret_cast<const float4*>(&sg[rowoff + 4]);
        const float4 h0 = *reinterpret_cast<const float4*>(&sh[rowoff]);
        const float4 h1 = *reinterpret_cast<const float4*>(&sh[rowoff + 4]);
        const float xf[8] = {f0.x, f0.y, f0.z, f0.w, f1.x, f1.y, f1.z, f1.w};
        const float xg[8] = {g0.x, g0.y, g0.z, g0.w, g1.x, g1.y, g1.z, g1.w};
        const float xh[8] = {h0.x, h0.y, h0.z, h0.w, h1.x, h1.y, h1.z, h1.w};

#pragma unroll
        for (int dj = 0; dj < 5; dj++) {
            const float rwa[PPT] = {cur[dj].x, cur[dj].y, cur[dj].z, cur[dj].w};
#pragma unroll
            for (int l = 0; l < PPT; l++) {
                const float w = rwa[l];
                ws[l] += w;
                const float a = xf[dj + l];
                s1f[l] = fmaf(w, a, s1f[l]);
                s2f[l] = fmaf(w * a, a, s2f[l]);
                const float gq = xg[dj + l];
                s1g[l] = fmaf(w, gq, s1g[l]);
                s2g[l] = fmaf(w * gq, gq, s2g[l]);
                const float hq = xh[dj + l];
                s1h[l] = fmaf(w, hq, s1h[l]);
            }
        }
#pragma unroll
        for (int j = 0; j < 5; j++) cur[j] = nxt[j];
    }

    // ---- wait for gray-max producers (long since done), reduce per-batch ----
    if (tid == 0) {
        while (*(volatile int*)&g_count < NPROD) { }
    }
    __syncthreads();
    __threadfence();
    if (tid < 32) {
        float m = g_gmax_partial[b * CH_PB + tid];   // CH_PB==32: one partial per lane
#pragma unroll
        for (int o = 16; o > 0; o >>= 1)
            m = fmaxf(m, __shfl_down_sync(0xFFFFFFFFu, m, o));
        if (tid == 0) s_gmax = m;
    }
    __syncthreads();
    const float cobj = s_gmax / ff;   // ALPHA = 1

    // ---- epilogue: per-pixel scalar, accumulate two sums ----
    float accA = 0.0f, accB = 0.0f;
#pragma unroll
    for (int l = 0; l < PPT; l++) {
        const float inv  = 1.0f / ws[l];
        const float muf  = s1f[l] * inv;
        const float vrf  = fmaxf(s2f[l] * inv - muf * muf, 0.0f);
        const float stdf = sqrtf(vrf + EPS);
        const float mug  = s1g[l] * inv;
        const float vrg  = fmaxf(s2g[l] * inv - mug * mug, 0.0f);
        const float stdg = sqrtf(vrg + EPS);
        const float muh  = s1h[l] * inv;
        const float obj  = cobj * stdg * (muh + EPS);
        const float r    = 1.0f - stdf / (stdf + obj);
        const float wblf = ws[l] - 1.0f;
        accA = fmaf(r, wblf, accA);
        accB += wblf;
    }

    // block reduction -> per-block partials
#pragma unroll
    for (int o = 16; o > 0; o >>= 1) {
        accA += __shfl_down_sync(0xFFFFFFFFu, accA, o);
        accB += __shfl_down_sync(0xFFFFFFFFu, accB, o);
    }
    const int wid = tid >> 5, lane = tid & 31;
    if (lane == 0) { redA[wid] = accA; redB[wid] = accB; }
    __syncthreads();
    if (wid == 0) {
        accA = (lane < BY) ? redA[lane] : 0.0f;
        accB = (lane < BY) ? redB[lane] : 0.0f;
#pragma unroll
        for (int o = 4; o > 0; o >>= 1) {
            accA += __shfl_down_sync(0xFFFFFFFFu, accA, o);
            accB += __shfl_down_sync(0xFFFFFFFFu, accB, o);
        }
        if (lane == 0) {
            g_blockA[lbid] = accA;
            g_blockB[lbid] = accB;
        }
    }
}

__global__ void finalize_kernel(float* __restrict__ out) {
    cudaGridDependencySynchronize();   // PDL: wait for main's partials

    const int t = threadIdx.x;   // 512 threads, NBLK_MAIN = 1024
    float a    = g_blockA[t] + g_blockA[t + 512];
    float bsum = g_blockB[t] + g_blockB[t + 512];
#pragma unroll
    for (int o = 16; o > 0; o >>= 1) {
        a    += __shfl_down_sync(0xFFFFFFFFu, a, o);
        bsum += __shfl_down_sync(0xFFFFFFFFu, bsum, o);
    }
    __shared__ float rA[16], rB[16];
    const int wid = t >> 5, lane = t & 31;
    if (lane == 0) { rA[wid] = a; rB[wid] = bsum; }
    __syncthreads();
    if (wid == 0) {
        a    = (lane < 16) ? rA[lane] : 0.0f;
        bsum = (lane < 16) ? rB[lane] : 0.0f;
#pragma unroll
        for (int o = 8; o > 0; o >>= 1) {
            a    += __shfl_down_sync(0xFFFFFFFFu, a, o);
            bsum += __shfl_down_sync(0xFFFFFFFFu, bsum, o);
        }
        if (lane == 0) {
            out[0] = a / bsum;
            g_count = 0;               // reset for next graph replay
        }
    }
}

extern "C" void kernel_launch(void* const* d_in, const int* in_sizes, int n_in,
                              void* d_out, int out_size) {
    const float* fake      = (const float*)d_in[0];
    const float* gamma_hdr = (const float*)d_in[1];
    const float* hdr_im    = (const float*)d_in[2];
    const float* r_weights = (const float*)d_in[3];
    const float* f_factors = (const float*)d_in[4];
    const float* gray      = (const float*)d_in[5];
    float* out = (float*)d_out;

    {
        cudaLaunchConfig_t cfg = {};
        cfg.gridDim  = dim3(W_IMG / TILE_W, H_IMG / TILE_H, NB);
        cfg.blockDim = dim3(BX, BY);
        cudaLaunchKernelEx(&cfg, intensity_loss_main,
                           fake, gamma_hdr, hdr_im, r_weights, f_factors, gray);
    }
    {
        cudaLaunchAttribute attr;
        attr.id = cudaLaunchAttributeProgrammaticStreamSerialization;
        attr.val.programmaticStreamSerializationAllowed = 1;
        cudaLaunchConfig_t cfg = {};
        cfg.gridDim  = dim3(1);
        cfg.blockDim = dim3(512);
        cfg.attrs    = &attr;
        cfg.numAttrs = 1;
        cudaLaunchKernelEx(&cfg, finalize_kernel, out);
    }
}